// round 2
// baseline (speedup 1.0000x reference)
#include <cuda_runtime.h>
#include <cstdint>
#include <cfloat>

#define N_ROWS 65536
#define DIM    1024
#define KCB    8192

#define BM 128
#define BN 128
#define BK 16
#define TM 8
#define TN 8
// threads per block = (BM/TM)*(BN/TN) = 16*16 = 256

#define TAU     2.0e-3f   // pass-1 margin threshold (33x fp32 noise sigma)
#define TAU2    2.0e-3f   // refine candidate window
#define WL_CAP  2048
#define MAX_CAND 64

// Scratch (allocation-free rule: __device__ globals)
__device__ float g_cbT[(size_t)KCB * DIM];   // 32 MB: codebook transposed [K][D]
__device__ int   g_argmin[N_ROWS];           // per-row argmin index
__device__ int   g_wl[WL_CAP];               // ambiguous-row worklist
__device__ int   g_wl_count;

// ---------------------------------------------------------------------------
// Kernel 1: transpose codebook [DIM][KCB] -> g_cbT [KCB][DIM]; reset worklist.
// ---------------------------------------------------------------------------
__global__ void vq_transpose_kernel(const float* __restrict__ cb) {
    if (blockIdx.x == 0 && blockIdx.y == 0 && threadIdx.x == 0 && threadIdx.y == 0)
        g_wl_count = 0;
    __shared__ float tile[32][33];
    const int kBase = blockIdx.x * 32;
    const int dBase = blockIdx.y * 32;
    const int tx = threadIdx.x;   // 0..31
    const int ty = threadIdx.y;   // 0..7
#pragma unroll
    for (int i = 0; i < 4; i++) {
        tile[ty + i * 8][tx] = cb[(size_t)(dBase + ty + i * 8) * KCB + (kBase + tx)];
    }
    __syncthreads();
#pragma unroll
    for (int i = 0; i < 4; i++) {
        g_cbT[(size_t)(kBase + ty + i * 8) * DIM + (dBase + tx)] = tile[tx][ty + i * 8];
    }
}

// ---------------------------------------------------------------------------
// Kernel 2: fused fp32 GEMM-NT (A=z [N,D], B=g_cbT [K,D]) + running argmin
//           + runner-up margin tracking. Ambiguous rows -> worklist.
// ---------------------------------------------------------------------------
__global__ __launch_bounds__(256, 2)
void vq_argmin_kernel(const float* __restrict__ A) {
    __shared__ float As[BK][BM];
    __shared__ float Bs[BK][BN];
    __shared__ float sBest[BM][16];
    __shared__ int   sIdx[BM][16];
    __shared__ float sSec[BM][16];

    const int tid = threadIdx.x;
    const int tx = tid & 15;        // col group (0..15)
    const int ty = tid >> 4;        // row group (0..15)
    const int rowBase = blockIdx.x * BM;

    float best[TM], sec[TM];
    int   bidx[TM];
#pragma unroll
    for (int i = 0; i < TM; i++) { best[i] = FLT_MAX; sec[i] = FLT_MAX; bidx[i] = 0; }

    for (int kt = 0; kt < KCB / BN; kt++) {
        const int colBase = kt * BN;

        float acc[TM][TN];
#pragma unroll
        for (int i = 0; i < TM; i++)
#pragma unroll
            for (int j = 0; j < TN; j++) acc[i][j] = 0.0f;

        for (int dB = 0; dB < DIM; dB += BK) {
#pragma unroll
            for (int r = 0; r < 2; r++) {
                const int i4  = tid + r * 256;       // 0..511
                const int row = i4 >> 2;             // 0..127
                const int c4  = (i4 & 3) * 4;        // 0,4,8,12
                float4 av = *(const float4*)&A[(size_t)(rowBase + row) * DIM + dB + c4];
                As[c4 + 0][row] = av.x;
                As[c4 + 1][row] = av.y;
                As[c4 + 2][row] = av.z;
                As[c4 + 3][row] = av.w;
                float4 bv = *(const float4*)&g_cbT[(size_t)(colBase + row) * DIM + dB + c4];
                Bs[c4 + 0][row] = bv.x;
                Bs[c4 + 1][row] = bv.y;
                Bs[c4 + 2][row] = bv.z;
                Bs[c4 + 3][row] = bv.w;
            }
            __syncthreads();

#pragma unroll
            for (int kk = 0; kk < BK; kk++) {
                float ra[TM], rb[TN];
#pragma unroll
                for (int i = 0; i < TM; i += 4) {
                    float4 v = *(const float4*)&As[kk][ty * TM + i];
                    ra[i + 0] = v.x; ra[i + 1] = v.y; ra[i + 2] = v.z; ra[i + 3] = v.w;
                }
#pragma unroll
                for (int j = 0; j < TN; j += 4) {
                    float4 v = *(const float4*)&Bs[kk][tx * TN + j];
                    rb[j + 0] = v.x; rb[j + 1] = v.y; rb[j + 2] = v.z; rb[j + 3] = v.w;
                }
#pragma unroll
                for (int i = 0; i < TM; i++)
#pragma unroll
                    for (int j = 0; j < TN; j++)
                        acc[i][j] = fmaf(ra[i], rb[j], acc[i][j]);
            }
            __syncthreads();
        }

        // Fold this K-tile into running (best, second, idx) per row slice
#pragma unroll
        for (int i = 0; i < TM; i++) {
#pragma unroll
            for (int j = 0; j < TN; j++) {
                const float v = acc[i][j];
                if (v < best[i]) {
                    sec[i] = best[i];
                    best[i] = v;
                    bidx[i] = colBase + tx * TN + j;
                } else if (v < sec[i]) {
                    sec[i] = v;
                }
            }
        }
    }

    // Cross-thread reduce: 16 tx-threads share each set of 8 rows
#pragma unroll
    for (int i = 0; i < TM; i++) {
        sBest[ty * TM + i][tx] = best[i];
        sIdx[ty * TM + i][tx]  = bidx[i];
        sSec[ty * TM + i][tx]  = sec[i];
    }
    __syncthreads();

    if (tid < BM) {
        float gb = sBest[tid][0];
        int   gi = sIdx[tid][0];
        float gs = sSec[tid][0];
#pragma unroll
        for (int t = 1; t < 16; t++) {
            const float b = sBest[tid][t];
            const int   i = sIdx[tid][t];
            const float s = sSec[tid][t];
            if (b < gb || (b == gb && i < gi)) {
                gs = fminf(gs, gb);
                gb = b; gi = i;
                gs = fminf(gs, s);
            } else {
                gs = fminf(gs, fminf(b, s));
            }
        }
        g_argmin[rowBase + tid] = gi;
        if (gs - gb < TAU) {
            const int p = atomicAdd(&g_wl_count, 1);
            if (p < WL_CAP) g_wl[p] = rowBase + tid;
        }
    }
}

// ---------------------------------------------------------------------------
// Kernel 2b: refine ambiguous rows. One block per worklist entry (loop-strided).
// fp32 full rescore -> shortlist -> exact fp64 on shortlist.
// ---------------------------------------------------------------------------
__global__ __launch_bounds__(256)
void vq_refine_kernel(const float* __restrict__ A) {
    __shared__ float  zs[DIM];            // 4 KB
    __shared__ float  dots[KCB];          // 32 KB
    __shared__ float  red[256];
    __shared__ int    cands[MAX_CAND];
    __shared__ double cval[MAX_CAND];
    __shared__ int    ncand;

    const int tid  = threadIdx.x;
    const int lane = tid & 31;
    const int wrp  = tid >> 5;
    const int cnt  = min(g_wl_count, WL_CAP);

    for (int wi = blockIdx.x; wi < cnt; wi += gridDim.x) {
        const int row = g_wl[wi];

        // Load z row
#pragma unroll
        for (int i = 0; i < DIM / 256; i++) zs[tid + i * 256] = A[(size_t)row * DIM + tid + i * 256];
        if (tid == 0) ncand = 0;
        __syncthreads();

        // fp32 rescore of all codewords (codebook rows are L2-resident)
        const float4* z4 = (const float4*)zs;
        float localMin = FLT_MAX;
        for (int k = tid; k < KCB; k += 256) {
            const float4* c4 = (const float4*)(g_cbT + (size_t)k * DIM);
            float s = 0.0f;
#pragma unroll 8
            for (int d = 0; d < DIM / 4; d++) {
                const float4 c = c4[d];
                const float4 z = z4[d];
                s = fmaf(c.x, z.x, s);
                s = fmaf(c.y, z.y, s);
                s = fmaf(c.z, z.z, s);
                s = fmaf(c.w, z.w, s);
            }
            dots[k] = s;
            localMin = fminf(localMin, s);
        }
        red[tid] = localMin;
        __syncthreads();
        for (int off = 128; off > 0; off >>= 1) {
            if (tid < off) red[tid] = fminf(red[tid], red[tid + off]);
            __syncthreads();
        }
        const float bmin = red[0];

        // Shortlist candidates near the min
        for (int k = tid; k < KCB; k += 256) {
            if (dots[k] < bmin + TAU2) {
                const int p = atomicAdd(&ncand, 1);
                if (p < MAX_CAND) cands[p] = k;
            }
        }
        __syncthreads();
        const int nc = min(ncand, MAX_CAND);

        // Exact fp64 rescore of candidates: one warp per candidate
        for (int ci = wrp; ci < nc; ci += 8) {
            const int k = cands[ci];
            const float* cb = g_cbT + (size_t)k * DIM;
            double s = 0.0;
            for (int d = lane; d < DIM; d += 32)
                s += (double)cb[d] * (double)zs[d];
#pragma unroll
            for (int off = 16; off > 0; off >>= 1)
                s += __shfl_down_sync(0xFFFFFFFFu, s, off);
            if (lane == 0) cval[ci] = s;
        }
        __syncthreads();

        if (tid == 0) {
            double bv = cval[0];
            int    bi = cands[0];
            for (int c = 1; c < nc; c++) {
                const double v = cval[c];
                const int    x = cands[c];
                if (v < bv || (v == bv && x < bi)) { bv = v; bi = x; }
            }
            g_argmin[row] = bi;
        }
        __syncthreads();
    }
}

// ---------------------------------------------------------------------------
// Kernel 3: gather out[n][:] = g_cbT[argmin[n]][:]
// ---------------------------------------------------------------------------
__global__ void vq_gather_kernel(float* __restrict__ out) {
    const int n = blockIdx.x;
    const int idx = g_argmin[n];
    const float4* src = (const float4*)(g_cbT + (size_t)idx * DIM);
    float4* dst = (float4*)(out + (size_t)n * DIM);
    dst[threadIdx.x] = src[threadIdx.x];   // 256 threads * float4 = 1024 floats
}

// ---------------------------------------------------------------------------
extern "C" void kernel_launch(void* const* d_in, const int* in_sizes, int n_in,
                              void* d_out, int out_size) {
    const float* z  = (const float*)d_in[0];   // [16,4096,1024] fp32
    const float* cb = (const float*)d_in[1];   // [1024,8192] fp32
    float* out = (float*)d_out;                // [16,4096,1024] fp32

    dim3 tgrid(KCB / 32, DIM / 32);
    dim3 tblk(32, 8);
    vq_transpose_kernel<<<tgrid, tblk>>>(cb);

    vq_argmin_kernel<<<N_ROWS / BM, 256>>>(z);

    vq_refine_kernel<<<512, 256>>>(z);

    vq_gather_kernel<<<N_ROWS, 256>>>(out);
}

// round 5
// speedup vs baseline: 3.3412x; 3.3412x over previous
#include <cuda_runtime.h>
#include <cuda_bf16.h>
#include <cstdint>
#include <cfloat>

#define N_ROWS 65536
#define DIM    1024
#define KCB    8192

#define TAU      2.0e-3f
#define TAU2     2.0e-3f
#define WL_CAP   4096
#define MAX_CAND 64

// ---- HMMA GEMM tiling ----
#define BM 128
#define BN 128
#define KC 64
#define N_TILES (KCB / BN)                      // 64
#define CHUNKS_PER_TILE (DIM / KC)              // 16
#define TOTAL_CHUNKS (N_TILES * CHUNKS_PER_TILE) // 1024
#define GEMM_THREADS 256

// ---- dynamic SMEM layout (bytes) ----
#define TILE_BYTES   16384            // 128 rows x 64 bf16 (128B rows, SW128)
#define SM_A_HI      0
#define SM_A_LO      16384
#define SM_B_HI      32768
#define SM_B_LO      49152
#define STAGE_BYTES  65536
#define SM_STAGE0    0
#define SM_EPI       (2 * STAGE_BYTES)          // 131072
#define EPI_B        0                          // float[128*4]
#define EPI_S        2048                       // float[128*4]
#define EPI_I        4096                       // int[128*4]
#define GEMM_SMEM    (SM_EPI + 6144)            // 137216

// ---- scratch (__device__ globals; allocation-free rule) ----
__device__ __nv_bfloat16 g_zhi[(size_t)N_ROWS * DIM];
__device__ __nv_bfloat16 g_zlo[(size_t)N_ROWS * DIM];
__device__ __nv_bfloat16 g_cbhi[(size_t)KCB * DIM];
__device__ __nv_bfloat16 g_cblo[(size_t)KCB * DIM];
__device__ float g_cbT[(size_t)KCB * DIM];
__device__ int   g_argmin[N_ROWS];
__device__ int   g_wl[WL_CAP];
__device__ int   g_wl_count;

// ============================ helpers ============================
__device__ __forceinline__ uint32_t smem_to_u32(const void* p) {
    uint32_t a;
    asm("{ .reg .u64 t; cvta.to.shared.u64 t, %1; cvt.u32.u64 %0, t; }" : "=r"(a) : "l"(p));
    return a;
}
#define SWZ128(o) ((o) ^ (((o) >> 3) & 0x70))

#define CP_ASYNC16(sm, g) \
    asm volatile("cp.async.cg.shared.global [%0], [%1], 16;" :: "r"(sm), "l"(g) : "memory")
#define CP_COMMIT()  asm volatile("cp.async.commit_group;" ::: "memory")
#define CP_WAIT1()   asm volatile("cp.async.wait_group 1;" ::: "memory")
#define CP_WAIT0()   asm volatile("cp.async.wait_group 0;" ::: "memory")

#define LDMATRIX_X4(r0, r1, r2, r3, a) \
    asm volatile("ldmatrix.sync.aligned.m8n8.x4.shared.b16 {%0,%1,%2,%3}, [%4];" \
                 : "=r"(r0), "=r"(r1), "=r"(r2), "=r"(r3) : "r"(a))

#define MMA_BF16(c0, c1, c2, c3, a0, a1, a2, a3, b0, b1) \
    asm volatile("mma.sync.aligned.m16n8k16.row.col.f32.bf16.bf16.f32 " \
                 "{%0,%1,%2,%3}, {%4,%5,%6,%7}, {%8,%9}, {%0,%1,%2,%3};" \
                 : "+f"(c0), "+f"(c1), "+f"(c2), "+f"(c3) \
                 : "r"(a0), "r"(a1), "r"(a2), "r"(a3), "r"(b0), "r"(b1))

// ---------------------------------------------------------------------------
// Prep 1: transpose codebook + fp32/bf16-hi/bf16-lo split; reset worklist.
// ---------------------------------------------------------------------------
__global__ void vq_prep_cb(const float* __restrict__ cb) {
    if (blockIdx.x == 0 && blockIdx.y == 0 && threadIdx.x == 0 && threadIdx.y == 0)
        g_wl_count = 0;
    __shared__ float tile[32][33];
    const int kBase = blockIdx.x * 32;
    const int dBase = blockIdx.y * 32;
    const int tx = threadIdx.x, ty = threadIdx.y;
#pragma unroll
    for (int i = 0; i < 4; i++)
        tile[ty + i * 8][tx] = cb[(size_t)(dBase + ty + i * 8) * KCB + (kBase + tx)];
    __syncthreads();
#pragma unroll
    for (int i = 0; i < 4; i++) {
        const float v = tile[tx][ty + i * 8];
        const size_t o = (size_t)(kBase + ty + i * 8) * DIM + (dBase + tx);
        g_cbT[o] = v;
        const __nv_bfloat16 h = __float2bfloat16(v);
        g_cbhi[o] = h;
        g_cblo[o] = __float2bfloat16(v - __bfloat162float(h));
    }
}

// ---------------------------------------------------------------------------
// Prep 2: split z into bf16 hi/lo.
// ---------------------------------------------------------------------------
__global__ void vq_prep_z(const float* __restrict__ z) {
    const size_t total4 = (size_t)N_ROWS * DIM / 4;
    const size_t stride = (size_t)gridDim.x * blockDim.x;
    const float4* z4 = (const float4*)z;
    __nv_bfloat162* hi2 = (__nv_bfloat162*)g_zhi;
    __nv_bfloat162* lo2 = (__nv_bfloat162*)g_zlo;
    for (size_t t = (size_t)blockIdx.x * blockDim.x + threadIdx.x; t < total4; t += stride) {
        const float4 v = z4[t];
        const __nv_bfloat16 h0 = __float2bfloat16(v.x), h1 = __float2bfloat16(v.y);
        const __nv_bfloat16 h2 = __float2bfloat16(v.z), h3 = __float2bfloat16(v.w);
        hi2[t * 2 + 0] = __nv_bfloat162(h0, h1);
        hi2[t * 2 + 1] = __nv_bfloat162(h2, h3);
        lo2[t * 2 + 0] = __nv_bfloat162(__float2bfloat16(v.x - __bfloat162float(h0)),
                                        __float2bfloat16(v.y - __bfloat162float(h1)));
        lo2[t * 2 + 1] = __nv_bfloat162(__float2bfloat16(v.z - __bfloat162float(h2)),
                                        __float2bfloat16(v.w - __bfloat162float(h3)));
    }
}

// ---------------------------------------------------------------------------
// Main: HMMA bf16 3-pass GEMM (ah*bh + ah*bl + al*bh) + fused argmin.
// One CTA per 128 rows; loops over 64 N-tiles of 128 codewords.
// ---------------------------------------------------------------------------
__global__ __launch_bounds__(GEMM_THREADS)
void vq_hmma_kernel() {
    extern __shared__ char smem[];
    const uint32_t sb = smem_to_u32(smem);
    const int tid  = threadIdx.x;
    const int wid  = tid >> 5;
    const int lane = tid & 31;
    const int wm   = wid >> 2;            // 0..1 (M group of 64)
    const int wn   = wid & 3;             // 0..3 (N group of 32)
    const int t4   = lane >> 2;           // 0..7
    const int tq   = lane & 3;            // 0..3
    const int rowBase = blockIdx.x * BM;

    // per-chunk loader: 16 x 16B cp.async per thread
    auto load_chunk = [&](int C) {
        const int nt = C >> 4, c = C & 15, s = C & 1;
        const uint32_t stage = sb + SM_STAGE0 + s * STAGE_BYTES;
        const int koff = c * KC;
        const int ntBase = nt * BN;
#pragma unroll
        for (int i = 0; i < 4; i++) {
            const int sg = tid + i * 256;        // 0..1023
            const int row = sg >> 3, sc = sg & 7;
            const uint32_t so = SWZ128(row * 128 + sc * 16);
            const size_t ga = (size_t)(rowBase + row) * DIM + koff + sc * 8;
            const size_t gb = (size_t)(ntBase + row) * DIM + koff + sc * 8;
            CP_ASYNC16(stage + SM_A_HI + so, g_zhi + ga);
            CP_ASYNC16(stage + SM_A_LO + so, g_zlo + ga);
            CP_ASYNC16(stage + SM_B_HI + so, g_cbhi + gb);
            CP_ASYNC16(stage + SM_B_LO + so, g_cblo + gb);
        }
        CP_COMMIT();
    };

    float acc[4][4][4];
    float rBest = FLT_MAX, rSec = FLT_MAX;
    int   rIdx = 0x7FFFFFFF;

    // ldmatrix lane-address components
    const int am  = lane >> 3;            // matrix id 0..3
    const int ar  = lane & 7;             // row within matrix
    const int aRow = ((am & 1) << 3) + ar;        // A: matrices 0/1 = m+0/m+8 (k0-7); 2/3 = m+0/m+8 (k8-15)
    const int aColB = (am >> 1) << 4;
    // B (non-trans, k-contiguous): matrices 0/1 = n+0..7 at k0-7/k8-15; 2/3 = n+8..15
    const int bRow = ((am >> 1) << 3) + ar;
    const int bColB = (am & 1) << 4;

    load_chunk(0);
    load_chunk(1);

    for (int C = 0; C < TOTAL_CHUNKS; C++) {
        const int s = C & 1, nt = C >> 4, c = C & 15;

        if (C < TOTAL_CHUNKS - 1) { CP_WAIT1(); } else { CP_WAIT0(); }
        __syncthreads();

        if (c == 0) {
#pragma unroll
            for (int mi = 0; mi < 4; mi++)
#pragma unroll
                for (int ni = 0; ni < 4; ni++)
#pragma unroll
                    for (int r = 0; r < 4; r++) acc[mi][ni][r] = 0.0f;
        }

        const uint32_t stage = sb + SM_STAGE0 + s * STAGE_BYTES;
        const uint32_t aHi = stage + SM_A_HI, aLo = stage + SM_A_LO;
        const uint32_t bHi = stage + SM_B_HI, bLo = stage + SM_B_LO;

#pragma unroll
        for (int ks = 0; ks < 4; ks++) {
            const int kb = ks * 32;       // 16 bf16 = 32 bytes per k-step
            uint32_t ah[16], bh[16], xf[16];

            // A_hi fragments (4 mi)
#pragma unroll
            for (int mi = 0; mi < 4; mi++) {
                const int row = wm * 64 + mi * 16 + aRow;
                const uint32_t ad = aHi + SWZ128(row * 128 + kb + aColB);
                LDMATRIX_X4(ah[mi*4+0], ah[mi*4+1], ah[mi*4+2], ah[mi*4+3], ad);
            }
            // B_hi fragments (4 ni via 2 non-trans x4): r0,r1 = b0,b1 of ni even;
            // r2,r3 = b0,b1 of ni odd -> stored at np*8 {+0,+1,+4,+5}
#pragma unroll
            for (int np = 0; np < 2; np++) {
                const int nrow = wn * 32 + np * 16 + bRow;
                const uint32_t bd = bHi + SWZ128(nrow * 128 + kb + bColB);
                LDMATRIX_X4(bh[np*8+0], bh[np*8+1], bh[np*8+4], bh[np*8+5], bd);
            }

            // pass 0: ah * bh
#pragma unroll
            for (int mi = 0; mi < 4; mi++)
#pragma unroll
                for (int ni = 0; ni < 4; ni++)
                    MMA_BF16(acc[mi][ni][0], acc[mi][ni][1], acc[mi][ni][2], acc[mi][ni][3],
                             ah[mi*4+0], ah[mi*4+1], ah[mi*4+2], ah[mi*4+3],
                             bh[ni*4+0], bh[ni*4+1]);

            // pass 1: al * bh
#pragma unroll
            for (int mi = 0; mi < 4; mi++) {
                const int row = wm * 64 + mi * 16 + aRow;
                const uint32_t ad = aLo + SWZ128(row * 128 + kb + aColB);
                LDMATRIX_X4(xf[mi*4+0], xf[mi*4+1], xf[mi*4+2], xf[mi*4+3], ad);
            }
#pragma unroll
            for (int mi = 0; mi < 4; mi++)
#pragma unroll
                for (int ni = 0; ni < 4; ni++)
                    MMA_BF16(acc[mi][ni][0], acc[mi][ni][1], acc[mi][ni][2], acc[mi][ni][3],
                             xf[mi*4+0], xf[mi*4+1], xf[mi*4+2], xf[mi*4+3],
                             bh[ni*4+0], bh[ni*4+1]);

            // pass 2: ah * bl
#pragma unroll
            for (int np = 0; np < 2; np++) {
                const int nrow = wn * 32 + np * 16 + bRow;
                const uint32_t bd = bLo + SWZ128(nrow * 128 + kb + bColB);
                LDMATRIX_X4(xf[np*8+0], xf[np*8+1], xf[np*8+4], xf[np*8+5], bd);
            }
#pragma unroll
            for (int mi = 0; mi < 4; mi++)
#pragma unroll
                for (int ni = 0; ni < 4; ni++)
                    MMA_BF16(acc[mi][ni][0], acc[mi][ni][1], acc[mi][ni][2], acc[mi][ni][3],
                             ah[mi*4+0], ah[mi*4+1], ah[mi*4+2], ah[mi*4+3],
                             xf[ni*4+0], xf[ni*4+1]);
        }
        __syncthreads();

        if (C + 2 < TOTAL_CHUNKS) load_chunk(C + 2);

        // ---- n-tile epilogue: fold acc into per-row running (best, sec, idx) ----
        if (c == 15) {
            float* eB = (float*)(smem + SM_EPI + EPI_B);
            float* eS = (float*)(smem + SM_EPI + EPI_S);
            int*   eI = (int*)(smem + SM_EPI + EPI_I);
            const int colBase = nt * BN + wn * 32 + tq * 2;

#pragma unroll
            for (int mi = 0; mi < 4; mi++) {
#pragma unroll
                for (int half = 0; half < 2; half++) {
                    const int row = wm * 64 + mi * 16 + half * 8 + t4;  // 0..127
                    float b = FLT_MAX, sv = FLT_MAX;
                    int   bi = 0x7FFFFFFF;
#pragma unroll
                    for (int ni = 0; ni < 4; ni++) {
#pragma unroll
                        for (int cc = 0; cc < 2; cc++) {
                            const float v = acc[mi][ni][half * 2 + cc];
                            const int col = colBase + ni * 8 + cc;
                            if (v < b) { sv = b; b = v; bi = col; }
                            else       { sv = fminf(sv, v); }
                        }
                    }
                    // quad reduce (lanes tq=0..3 share the row)
#pragma unroll
                    for (int off = 1; off <= 2; off <<= 1) {
                        const float ob = __shfl_xor_sync(0xFFFFFFFFu, b, off);
                        const float os = __shfl_xor_sync(0xFFFFFFFFu, sv, off);
                        const int   oi = __shfl_xor_sync(0xFFFFFFFFu, bi, off);
                        if (ob < b || (ob == b && oi < bi)) {
                            sv = fminf(b, os); b = ob; bi = oi;
                        } else {
                            sv = fminf(sv, ob);
                        }
                    }
                    if (tq == 0) {
                        eB[row * 4 + wn] = b;
                        eS[row * 4 + wn] = sv;
                        eI[row * 4 + wn] = bi;
                    }
                }
            }
            __syncthreads();
            if (tid < BM) {
#pragma unroll
                for (int w = 0; w < 4; w++) {
                    const float b = eB[tid * 4 + w];
                    const float sv = eS[tid * 4 + w];
                    const int   bi = eI[tid * 4 + w];
                    if (b < rBest || (b == rBest && bi < rIdx)) {
                        rSec = fminf(rBest, sv);
                        rBest = b; rIdx = bi;
                    } else {
                        rSec = fminf(rSec, fminf(b, sv));
                    }
                }
            }
            __syncthreads();
        }
    }

    if (tid < BM) {
        const int row = rowBase + tid;
        g_argmin[row] = rIdx;
        if (rSec - rBest < TAU) {
            const int p = atomicAdd(&g_wl_count, 1);
            if (p < WL_CAP) g_wl[p] = row;
        }
    }
}

// ---------------------------------------------------------------------------
// Refine ambiguous rows: fp32 full rescore -> shortlist -> exact fp64.
// ---------------------------------------------------------------------------
__global__ __launch_bounds__(256)
void vq_refine_kernel(const float* __restrict__ A) {
    __shared__ float  zs[DIM];
    __shared__ float  dots[KCB];
    __shared__ float  red[256];
    __shared__ int    cands[MAX_CAND];
    __shared__ double cval[MAX_CAND];
    __shared__ int    ncand;

    const int tid  = threadIdx.x;
    const int lane = tid & 31;
    const int wrp  = tid >> 5;
    const int cnt  = min(g_wl_count, WL_CAP);

    for (int wi = blockIdx.x; wi < cnt; wi += gridDim.x) {
        const int row = g_wl[wi];
#pragma unroll
        for (int i = 0; i < DIM / 256; i++)
            zs[tid + i * 256] = A[(size_t)row * DIM + tid + i * 256];
        if (tid == 0) ncand = 0;
        __syncthreads();

        const float4* z4 = (const float4*)zs;
        float localMin = FLT_MAX;
        for (int k = tid; k < KCB; k += 256) {
            const float4* c4 = (const float4*)(g_cbT + (size_t)k * DIM);
            float sacc = 0.0f;
#pragma unroll 8
            for (int d = 0; d < DIM / 4; d++) {
                const float4 cc = c4[d];
                const float4 zz = z4[d];
                sacc = fmaf(cc.x, zz.x, sacc);
                sacc = fmaf(cc.y, zz.y, sacc);
                sacc = fmaf(cc.z, zz.z, sacc);
                sacc = fmaf(cc.w, zz.w, sacc);
            }
            dots[k] = sacc;
            localMin = fminf(localMin, sacc);
        }
        red[tid] = localMin;
        __syncthreads();
        for (int off = 128; off > 0; off >>= 1) {
            if (tid < off) red[tid] = fminf(red[tid], red[tid + off]);
            __syncthreads();
        }
        const float bmin = red[0];

        for (int k = tid; k < KCB; k += 256) {
            if (dots[k] < bmin + TAU2) {
                const int p = atomicAdd(&ncand, 1);
                if (p < MAX_CAND) cands[p] = k;
            }
        }
        __syncthreads();
        const int nc = min(ncand, MAX_CAND);

        for (int ci = wrp; ci < nc; ci += 8) {
            const int k = cands[ci];
            const float* cbp = g_cbT + (size_t)k * DIM;
            double sd = 0.0;
            for (int d = lane; d < DIM; d += 32)
                sd += (double)cbp[d] * (double)zs[d];
#pragma unroll
            for (int off = 16; off > 0; off >>= 1)
                sd += __shfl_down_sync(0xFFFFFFFFu, sd, off);
            if (lane == 0) cval[ci] = sd;
        }
        __syncthreads();

        if (tid == 0) {
            double bv = cval[0];
            int    bi = cands[0];
            for (int ci2 = 1; ci2 < nc; ci2++) {
                const double v = cval[ci2];
                const int    x = cands[ci2];
                if (v < bv || (v == bv && x < bi)) { bv = v; bi = x; }
            }
            g_argmin[row] = bi;
        }
        __syncthreads();
    }
}

// ---------------------------------------------------------------------------
// Gather: out[n][:] = g_cbT[argmin[n]][:]
// ---------------------------------------------------------------------------
__global__ void vq_gather_kernel(float* __restrict__ out) {
    const int n = blockIdx.x;
    const int idx = g_argmin[n];
    const float4* src = (const float4*)(g_cbT + (size_t)idx * DIM);
    float4* dst = (float4*)(out + (size_t)n * DIM);
    dst[threadIdx.x] = src[threadIdx.x];
}

// ---------------------------------------------------------------------------
extern "C" void kernel_launch(void* const* d_in, const int* in_sizes, int n_in,
                              void* d_out, int out_size) {
    const float* z  = (const float*)d_in[0];
    const float* cb = (const float*)d_in[1];
    float* out = (float*)d_out;

    cudaFuncSetAttribute(vq_hmma_kernel, cudaFuncAttributeMaxDynamicSharedMemorySize, GEMM_SMEM);

    dim3 tgrid(KCB / 32, DIM / 32);
    dim3 tblk(32, 8);
    vq_prep_cb<<<tgrid, tblk>>>(cb);
    vq_prep_z<<<8192, 256>>>(z);

    vq_hmma_kernel<<<N_ROWS / BM, GEMM_THREADS, GEMM_SMEM>>>();

    vq_refine_kernel<<<512, 256>>>(z);
    vq_gather_kernel<<<N_ROWS, 256>>>(out);
}